// round 1
// baseline (speedup 1.0000x reference)
#include <cuda_runtime.h>
#include <cuda_bf16.h>
#include <math.h>

#define N_NODES 100000
#define N_EDGES 1600000
#define F_IN   128
#define H1     200
#define H2     50
#define C_OUT  10
#define MAXDEG 128

// ---------------- scratch (static device allocations; no cudaMalloc) --------
__device__ int   g_cnt[N_NODES];                       // degree per dst node
__device__ int   g_bucket[(size_t)N_NODES * MAXDEG];   // src ids grouped by dst
__device__ float g_agg1[(size_t)N_NODES * F_IN];       // 51.2 MB
__device__ float g_h1  [(size_t)N_NODES * H1];         // 80 MB
__device__ float g_agg2[(size_t)N_NODES * H1];         // 80 MB
__device__ float g_h2  [(size_t)N_NODES * H2];         // 20 MB
__device__ float g_agg3[(size_t)N_NODES * H2];         // 20 MB

// ---------------- helpers ----------------------------------------------------
__global__ void zero_cnt_kernel() {
    int i = blockIdx.x * blockDim.x + threadIdx.x;
    if (i < N_NODES) g_cnt[i] = 0;
}

// Group edges by destination into fixed-stride buckets (order within a bucket
// is nondeterministic but max-aggregation is order-invariant).
__global__ void bucket_build_kernel(const int* __restrict__ src,
                                    const int* __restrict__ dst) {
    int e = blockIdx.x * blockDim.x + threadIdx.x;
    if (e >= N_EDGES) return;
    int d = dst[e];
    int p = atomicAdd(&g_cnt[d], 1);
    if (p < MAXDEG) g_bucket[(size_t)d * MAXDEG + p] = src[e];
}

// Warp-per-node gather-max aggregation. RV = ceil(F/32) feature registers/lane.
template <int F, int RV>
__global__ void agg_kernel(const float* __restrict__ x, float* __restrict__ agg) {
    int gwarp = (blockIdx.x * blockDim.x + threadIdx.x) >> 5;
    int lane  = threadIdx.x & 31;
    if (gwarp >= N_NODES) return;

    int c = g_cnt[gwarp];
    if (c > MAXDEG) c = MAXDEG;

    float m[RV];
#pragma unroll
    for (int r = 0; r < RV; r++) m[r] = -INFINITY;

    const int* bk = g_bucket + (size_t)gwarp * MAXDEG;
    for (int i = 0; i < c; i++) {
        int s = bk[i];                       // broadcast load
        const float* row = x + (size_t)s * F;
#pragma unroll
        for (int r = 0; r < RV; r++) {
            int f = lane + r * 32;
            if (f < F) m[r] = fmaxf(m[r], row[f]);   // coalesced per iteration
        }
    }

    float* out = agg + (size_t)gwarp * F;
#pragma unroll
    for (int r = 0; r < RV; r++) {
        int f = lane + r * 32;
        if (f < F) out[f] = (c == 0) ? 0.0f : m[r];  // empty segment -> 0 (PyG)
    }
}

// Fused dual GEMM: out[M,NN] = A1@W1 + A2@W2 + bias  (A row-major [M,K],
// W row-major [K,NN]). BM=BN=64, BK=8, 256 threads, 4x4 microtile.
__global__ void gemm_dual_kernel(const float* __restrict__ A1,
                                 const float* __restrict__ A2,
                                 const float* __restrict__ W1,
                                 const float* __restrict__ W2,
                                 const float* __restrict__ bias,
                                 float* __restrict__ out,
                                 int M, int K, int NN) {
    __shared__ float As[8][72];   // transposed A tile, stride 72 keeps 16B align
    __shared__ float Ws[8][72];

    int tid = threadIdx.x;
    int tx = tid & 15;            // 16 col groups
    int ty = tid >> 4;            // 16 row groups
    int rowBase = blockIdx.y * 64;
    int colBase = blockIdx.x * 64;

    float acc[4][4] = {};

    int K2 = 2 * K;               // concatenated [A1|A2] along K
    for (int kt = 0; kt < K2; kt += 8) {
        const float* A; const float* W; int ko;
        if (kt < K) { A = A1; W = W1; ko = kt; }
        else        { A = A2; W = W2; ko = kt - K; }

        // Load A tile (64 rows x 8 k), store transposed.  512 elems / 256 thr.
#pragma unroll
        for (int l = 0; l < 2; l++) {
            int idx = tid + l * 256;
            int r = idx >> 3, kk = idx & 7;
            int row = rowBase + r;
            float v = (row < M) ? A[(size_t)row * K + ko + kk] : 0.0f;
            As[kk][r] = v;
        }
        // Load W tile (8 k x 64 cols).
#pragma unroll
        for (int l = 0; l < 2; l++) {
            int idx = tid + l * 256;
            int kk = idx >> 6, cc = idx & 63;
            int col = colBase + cc;
            float v = (col < NN) ? W[(size_t)(ko + kk) * NN + col] : 0.0f;
            Ws[kk][cc] = v;
        }
        __syncthreads();

#pragma unroll
        for (int kk = 0; kk < 8; kk++) {
            float a[4], w[4];
#pragma unroll
            for (int i = 0; i < 4; i++) a[i] = As[kk][ty * 4 + i];
#pragma unroll
            for (int j = 0; j < 4; j++) w[j] = Ws[kk][tx * 4 + j];
#pragma unroll
            for (int i = 0; i < 4; i++)
#pragma unroll
                for (int j = 0; j < 4; j++)
                    acc[i][j] += a[i] * w[j];
        }
        __syncthreads();
    }

#pragma unroll
    for (int i = 0; i < 4; i++) {
        int row = rowBase + ty * 4 + i;
        if (row >= M) continue;
#pragma unroll
        for (int j = 0; j < 4; j++) {
            int col = colBase + tx * 4 + j;
            if (col < NN) out[(size_t)row * NN + col] = acc[i][j] + bias[col];
        }
    }
}

// Final layer (K=50 -> 10 logits) fused with log_softmax, thread-per-node.
__global__ void final_kernel(const float* __restrict__ agg,
                             const float* __restrict__ h,
                             const float* __restrict__ Wl,
                             const float* __restrict__ Wr,
                             const float* __restrict__ b,
                             float* __restrict__ out) {
    __shared__ float sWl[H2 * C_OUT], sWr[H2 * C_OUT], sb[C_OUT];
    for (int i = threadIdx.x; i < H2 * C_OUT; i += blockDim.x) {
        sWl[i] = Wl[i];
        sWr[i] = Wr[i];
    }
    if (threadIdx.x < C_OUT) sb[threadIdx.x] = b[threadIdx.x];
    __syncthreads();

    int n = blockIdx.x * blockDim.x + threadIdx.x;
    if (n >= N_NODES) return;

    float logit[C_OUT];
#pragma unroll
    for (int j = 0; j < C_OUT; j++) logit[j] = sb[j];

    const float* ar = agg + (size_t)n * H2;
    const float* hr = h   + (size_t)n * H2;
#pragma unroll 5
    for (int k = 0; k < H2; k++) {
        float a  = ar[k];
        float hh = hr[k];
#pragma unroll
        for (int j = 0; j < C_OUT; j++)
            logit[j] += a * sWl[k * C_OUT + j] + hh * sWr[k * C_OUT + j];
    }

    float mx = logit[0];
#pragma unroll
    for (int j = 1; j < C_OUT; j++) mx = fmaxf(mx, logit[j]);
    float s = 0.0f;
#pragma unroll
    for (int j = 0; j < C_OUT; j++) s += expf(logit[j] - mx);
    float lse = mx + logf(s);
#pragma unroll
    for (int j = 0; j < C_OUT; j++) out[(size_t)n * C_OUT + j] = logit[j] - lse;
}

// ---------------- launch ------------------------------------------------------
extern "C" void kernel_launch(void* const* d_in, const int* in_sizes, int n_in,
                              void* d_out, int out_size) {
    const float* x    = (const float*)d_in[0];
    const int*   ei   = (const int*)d_in[1];          // [2, E] row-major
    const float* W_l1 = (const float*)d_in[2];
    const float* b1   = (const float*)d_in[3];
    const float* W_r1 = (const float*)d_in[4];
    const float* W_l2 = (const float*)d_in[5];
    const float* b2   = (const float*)d_in[6];
    const float* W_r2 = (const float*)d_in[7];
    const float* W_l3 = (const float*)d_in[8];
    const float* b3   = (const float*)d_in[9];
    const float* W_r3 = (const float*)d_in[10];
    float* out = (float*)d_out;

    const int* src = ei;
    const int* dst = ei + N_EDGES;

    // Resolve device-symbol addresses for kernel args (pure query, no alloc).
    float *agg1, *h1, *agg2, *h2, *agg3;
    cudaGetSymbolAddress((void**)&agg1, g_agg1);
    cudaGetSymbolAddress((void**)&h1,   g_h1);
    cudaGetSymbolAddress((void**)&agg2, g_agg2);
    cudaGetSymbolAddress((void**)&h2,   g_h2);
    cudaGetSymbolAddress((void**)&agg3, g_agg3);

    // 1. build per-dst buckets
    zero_cnt_kernel<<<(N_NODES + 255) / 256, 256>>>();
    bucket_build_kernel<<<(N_EDGES + 255) / 256, 256>>>(src, dst);

    const int aggBlocks = (N_NODES * 32 + 255) / 256;

    // 2. layer 1: agg1 = segmax(x), h1 = agg1@W_l1 + x@W_r1 + b1
    agg_kernel<F_IN, 4><<<aggBlocks, 256>>>(x, agg1);
    {
        dim3 grid((H1 + 63) / 64, (N_NODES + 63) / 64);
        gemm_dual_kernel<<<grid, 256>>>(agg1, x, W_l1, W_r1, b1, h1,
                                        N_NODES, F_IN, H1);
    }

    // 3. layer 2
    agg_kernel<H1, 7><<<aggBlocks, 256>>>(h1, agg2);
    {
        dim3 grid((H2 + 63) / 64, (N_NODES + 63) / 64);
        gemm_dual_kernel<<<grid, 256>>>(agg2, h1, W_l2, W_r2, b2, h2,
                                        N_NODES, H1, H2);
    }

    // 4. layer 3 + log_softmax
    agg_kernel<H2, 2><<<aggBlocks, 256>>>(h2, agg3);
    final_kernel<<<(N_NODES + 255) / 256, 256>>>(agg3, h2, W_l3, W_r3, b3, out);
}

// round 2
// speedup vs baseline: 1.0967x; 1.0967x over previous
#include <cuda_runtime.h>
#include <cuda_bf16.h>
#include <math.h>

#define N_NODES 100000
#define N_EDGES 1600000
#define F_IN   128
#define H1     200
#define H2     50
#define C_OUT  10
#define MAXDEG 128

// ---------------- scratch (static device arrays; no cudaMalloc) -------------
__device__ int   g_cnt[N_NODES];
__device__ int   g_bucket[(size_t)N_NODES * MAXDEG];
__device__ float g_agg1[(size_t)N_NODES * F_IN];
__device__ float g_h1  [(size_t)N_NODES * H1];
__device__ float g_agg2[(size_t)N_NODES * H1];
__device__ float g_h2  [(size_t)N_NODES * H2];
__device__ float g_agg3[(size_t)N_NODES * H2];

// ---------------- bucket build ----------------------------------------------
__global__ void zero_cnt_kernel() {
    int i = blockIdx.x * blockDim.x + threadIdx.x;
    if (i < N_NODES) g_cnt[i] = 0;
}

__global__ void bucket_build_kernel(const int* __restrict__ src,
                                    const int* __restrict__ dst) {
    int e = blockIdx.x * blockDim.x + threadIdx.x;
    if (e >= N_EDGES) return;
    int d = dst[e];
    int p = atomicAdd(&g_cnt[d], 1);
    if (p < MAXDEG) g_bucket[(size_t)d * MAXDEG + p] = src[e];
}

// ---------------- aggregation: warp/node, float2 gather, unroll x2 ----------
template <int F>
__global__ void agg_kernel(const float* __restrict__ x, float* __restrict__ agg) {
    constexpr int C2 = F / 2;              // float2 chunks per row
    constexpr int RV = (C2 + 31) / 32;     // chunks per lane

    int gwarp = (blockIdx.x * blockDim.x + threadIdx.x) >> 5;
    int lane  = threadIdx.x & 31;
    if (gwarp >= N_NODES) return;

    int c = g_cnt[gwarp];
    if (c > MAXDEG) c = MAXDEG;

    float2 m[RV];
#pragma unroll
    for (int r = 0; r < RV; r++) { m[r].x = -INFINITY; m[r].y = -INFINITY; }

    const int* bk = g_bucket + (size_t)gwarp * MAXDEG;
    int i = 0;
    for (; i + 1 < c; i += 2) {
        int s0 = bk[i], s1 = bk[i + 1];
        const float2* r0 = (const float2*)(x + (size_t)s0 * F);
        const float2* r1 = (const float2*)(x + (size_t)s1 * F);
#pragma unroll
        for (int r = 0; r < RV; r++) {
            int ch = lane + r * 32;
            if (ch < C2) {
                float2 v0 = r0[ch];
                float2 v1 = r1[ch];
                m[r].x = fmaxf(m[r].x, fmaxf(v0.x, v1.x));
                m[r].y = fmaxf(m[r].y, fmaxf(v0.y, v1.y));
            }
        }
    }
    if (i < c) {
        const float2* r0 = (const float2*)(x + (size_t)bk[i] * F);
#pragma unroll
        for (int r = 0; r < RV; r++) {
            int ch = lane + r * 32;
            if (ch < C2) {
                float2 v0 = r0[ch];
                m[r].x = fmaxf(m[r].x, v0.x);
                m[r].y = fmaxf(m[r].y, v0.y);
            }
        }
    }

    float2* out = (float2*)(agg + (size_t)gwarp * F);
#pragma unroll
    for (int r = 0; r < RV; r++) {
        int ch = lane + r * 32;
        if (ch < C2) {
            float2 v = (c == 0) ? make_float2(0.f, 0.f) : m[r];
            out[ch] = v;
        }
    }
}

// ---------------- dual GEMM 128x128, 8x8 micro, float4 LDS ------------------
// out[M,NN] = A1@W1 + A2@W2 + bias.  K%8==0, NN%8==0 required.
__global__ __launch_bounds__(256, 2)
void gemm128_dual(const float* __restrict__ A1, const float* __restrict__ A2,
                  const float* __restrict__ W1, const float* __restrict__ W2,
                  const float* __restrict__ bias, float* __restrict__ out,
                  int M, int K, int NN) {
    constexpr int BM = 128, BN = 128, BK = 8, PAD = 4;
    __shared__ float As[BK][BM + PAD];
    __shared__ float Ws[BK][BN + PAD];

    int tid = threadIdx.x;
    int tx = tid & 15;          // 16 col groups of 8
    int ty = tid >> 4;          // 16 row groups of 8
    int rowBase = blockIdx.y * BM;
    int colBase = blockIdx.x * BN;

    int ar = tid >> 1;              // A: row within tile
    int ak = (tid & 1) * 4;         // A: k quad
    int wk = tid >> 5;              // W: k row
    int wc = (tid & 31) * 4;        // W: col quad

    float acc[8][8] = {};

    for (int kt = 0; kt < 2 * K; kt += BK) {
        const float* A; const float* W; int ko;
        if (kt < K) { A = A1; W = W1; ko = kt; }
        else        { A = A2; W = W2; ko = kt - K; }

        // A tile: one float4 per thread, store transposed.
        {
            int row = rowBase + ar;
            float4 v = make_float4(0.f, 0.f, 0.f, 0.f);
            if (row < M) v = *(const float4*)(A + (size_t)row * K + ko + ak);
            As[ak + 0][ar] = v.x; As[ak + 1][ar] = v.y;
            As[ak + 2][ar] = v.z; As[ak + 3][ar] = v.w;
        }
        // W tile: one float4 per thread.
        {
            int col = colBase + wc;
            float4 v = make_float4(0.f, 0.f, 0.f, 0.f);
            if (col < NN) v = *(const float4*)(W + (size_t)(ko + wk) * NN + col);
            *(float4*)&Ws[wk][wc] = v;
        }
        __syncthreads();

#pragma unroll
        for (int kk = 0; kk < BK; kk++) {
            float4 a0 = *(const float4*)&As[kk][ty * 8];
            float4 a1 = *(const float4*)&As[kk][ty * 8 + 4];
            float4 w0 = *(const float4*)&Ws[kk][tx * 8];
            float4 w1 = *(const float4*)&Ws[kk][tx * 8 + 4];
            float a[8] = {a0.x, a0.y, a0.z, a0.w, a1.x, a1.y, a1.z, a1.w};
            float w[8] = {w0.x, w0.y, w0.z, w0.w, w1.x, w1.y, w1.z, w1.w};
#pragma unroll
            for (int i = 0; i < 8; i++)
#pragma unroll
                for (int j = 0; j < 8; j++)
                    acc[i][j] += a[i] * w[j];
        }
        __syncthreads();
    }

#pragma unroll
    for (int i = 0; i < 8; i++) {
        int row = rowBase + ty * 8 + i;
        if (row >= M) continue;
#pragma unroll
        for (int jv = 0; jv < 8; jv += 4) {
            int col = colBase + tx * 8 + jv;
            if (col < NN) {
                float4 bv = *(const float4*)(bias + col);
                float4 o;
                o.x = acc[i][jv + 0] + bv.x;
                o.y = acc[i][jv + 1] + bv.y;
                o.z = acc[i][jv + 2] + bv.z;
                o.w = acc[i][jv + 3] + bv.w;
                *(float4*)(out + (size_t)row * NN + col) = o;
            }
        }
    }
}

// ---------------- dual GEMM 128x64, 8x4 micro (small-N layer) ---------------
__global__ __launch_bounds__(256, 2)
void gemm64_dual(const float* __restrict__ A1, const float* __restrict__ A2,
                 const float* __restrict__ W1, const float* __restrict__ W2,
                 const float* __restrict__ bias, float* __restrict__ out,
                 int M, int K, int NN) {
    constexpr int BM = 128, BN = 64, BK = 8, PAD = 4;
    __shared__ float As[BK][BM + PAD];
    __shared__ float Ws[BK][BN + PAD];

    int tid = threadIdx.x;
    int tx = tid & 15;          // 16 col groups of 4
    int ty = tid >> 4;          // 16 row groups of 8
    int rowBase = blockIdx.y * BM;
    int colBase = blockIdx.x * BN;

    int ar = tid >> 1;
    int ak = (tid & 1) * 4;
    int wk = tid >> 5;              // 0..7
    int wc = (tid & 31) * 2;        // col pair

    float acc[8][4] = {};

    for (int kt = 0; kt < 2 * K; kt += BK) {
        const float* A; const float* W; int ko;
        if (kt < K) { A = A1; W = W1; ko = kt; }
        else        { A = A2; W = W2; ko = kt - K; }

        {
            int row = rowBase + ar;
            float4 v = make_float4(0.f, 0.f, 0.f, 0.f);
            if (row < M) v = *(const float4*)(A + (size_t)row * K + ko + ak);
            As[ak + 0][ar] = v.x; As[ak + 1][ar] = v.y;
            As[ak + 2][ar] = v.z; As[ak + 3][ar] = v.w;
        }
        {
            int col = colBase + wc;
            float2 v = make_float2(0.f, 0.f);
            if (col < NN) v = *(const float2*)(W + (size_t)(ko + wk) * NN + col);
            *(float2*)&Ws[wk][wc] = v;
        }
        __syncthreads();

#pragma unroll
        for (int kk = 0; kk < BK; kk++) {
            float4 a0 = *(const float4*)&As[kk][ty * 8];
            float4 a1 = *(const float4*)&As[kk][ty * 8 + 4];
            float4 w0 = *(const float4*)&Ws[kk][tx * 4];
            float a[8] = {a0.x, a0.y, a0.z, a0.w, a1.x, a1.y, a1.z, a1.w};
            float w[4] = {w0.x, w0.y, w0.z, w0.w};
#pragma unroll
            for (int i = 0; i < 8; i++)
#pragma unroll
                for (int j = 0; j < 4; j++)
                    acc[i][j] += a[i] * w[j];
        }
        __syncthreads();
    }

#pragma unroll
    for (int i = 0; i < 8; i++) {
        int row = rowBase + ty * 8 + i;
        if (row >= M) continue;
#pragma unroll
        for (int j = 0; j < 4; j++) {
            int col = colBase + tx * 4 + j;
            if (col < NN)
                out[(size_t)row * NN + col] = acc[i][j] + bias[col];
        }
    }
}

// ---------------- final layer + log_softmax ---------------------------------
__global__ void final_kernel(const float* __restrict__ agg,
                             const float* __restrict__ h,
                             const float* __restrict__ Wl,
                             const float* __restrict__ Wr,
                             const float* __restrict__ b,
                             float* __restrict__ out) {
    __shared__ float sWl[H2 * C_OUT], sWr[H2 * C_OUT], sb[C_OUT];
    for (int i = threadIdx.x; i < H2 * C_OUT; i += blockDim.x) {
        sWl[i] = Wl[i];
        sWr[i] = Wr[i];
    }
    if (threadIdx.x < C_OUT) sb[threadIdx.x] = b[threadIdx.x];
    __syncthreads();

    int n = blockIdx.x * blockDim.x + threadIdx.x;
    if (n >= N_NODES) return;

    float logit[C_OUT];
#pragma unroll
    for (int j = 0; j < C_OUT; j++) logit[j] = sb[j];

    const float* ar = agg + (size_t)n * H2;
    const float* hr = h   + (size_t)n * H2;
#pragma unroll 5
    for (int k = 0; k < H2; k++) {
        float a  = ar[k];
        float hh = hr[k];
#pragma unroll
        for (int j = 0; j < C_OUT; j++)
            logit[j] += a * sWl[k * C_OUT + j] + hh * sWr[k * C_OUT + j];
    }

    float mx = logit[0];
#pragma unroll
    for (int j = 1; j < C_OUT; j++) mx = fmaxf(mx, logit[j]);
    float s = 0.0f;
#pragma unroll
    for (int j = 0; j < C_OUT; j++) s += expf(logit[j] - mx);
    float lse = mx + logf(s);
#pragma unroll
    for (int j = 0; j < C_OUT; j++) out[(size_t)n * C_OUT + j] = logit[j] - lse;
}

// ---------------- launch ----------------------------------------------------
extern "C" void kernel_launch(void* const* d_in, const int* in_sizes, int n_in,
                              void* d_out, int out_size) {
    const float* x    = (const float*)d_in[0];
    const int*   ei   = (const int*)d_in[1];
    const float* W_l1 = (const float*)d_in[2];
    const float* b1   = (const float*)d_in[3];
    const float* W_r1 = (const float*)d_in[4];
    const float* W_l2 = (const float*)d_in[5];
    const float* b2   = (const float*)d_in[6];
    const float* W_r2 = (const float*)d_in[7];
    const float* W_l3 = (const float*)d_in[8];
    const float* b3   = (const float*)d_in[9];
    const float* W_r3 = (const float*)d_in[10];
    float* out = (float*)d_out;

    const int* src = ei;
    const int* dst = ei + N_EDGES;

    float *agg1, *h1, *agg2, *h2, *agg3;
    cudaGetSymbolAddress((void**)&agg1, g_agg1);
    cudaGetSymbolAddress((void**)&h1,   g_h1);
    cudaGetSymbolAddress((void**)&agg2, g_agg2);
    cudaGetSymbolAddress((void**)&h2,   g_h2);
    cudaGetSymbolAddress((void**)&agg3, g_agg3);

    zero_cnt_kernel<<<(N_NODES + 255) / 256, 256>>>();
    bucket_build_kernel<<<(N_EDGES + 255) / 256, 256>>>(src, dst);

    const int aggBlocks = (N_NODES * 32 + 255) / 256;

    // layer 1
    agg_kernel<F_IN><<<aggBlocks, 256>>>(x, agg1);
    {
        dim3 grid((H1 + 127) / 128, (N_NODES + 127) / 128);
        gemm128_dual<<<grid, 256>>>(agg1, x, W_l1, W_r1, b1, h1,
                                    N_NODES, F_IN, H1);
    }

    // layer 2
    agg_kernel<H1><<<aggBlocks, 256>>>(h1, agg2);
    {
        dim3 grid((H2 + 63) / 64, (N_NODES + 127) / 128);
        gemm64_dual<<<grid, 256>>>(agg2, h1, W_l2, W_r2, b2, h2,
                                   N_NODES, H1, H2);
    }

    // layer 3 + log_softmax
    agg_kernel<H2><<<aggBlocks, 256>>>(h2, agg3);
    final_kernel<<<(N_NODES + 255) / 256, 256>>>(agg3, h2, W_l3, W_r3, b3, out);
}

// round 3
// speedup vs baseline: 1.1268x; 1.0275x over previous
#include <cuda_runtime.h>
#include <cuda_bf16.h>
#include <math.h>

#define N_NODES 100000
#define N_EDGES 1600000
#define F_IN   128
#define H1     200
#define H2     50
#define C_OUT  10
#define MAXDEG 128

typedef unsigned long long ull;

// fma.rn.f32x2: two IEEE fp32 FMAs in one instruction (sm_100+ packed math).
#define FMA_F32X2(c, a, b) \
    asm("fma.rn.f32x2 %0, %1, %2, %0;" : "+l"(c) : "l"(a), "l"(b))
// splat one fp32 into both lanes of a 64-bit pair
#define SPLAT_F32X2(d, s) \
    asm("mov.b64 %0, {%1, %1};" : "=l"(d) : "r"(__float_as_uint(s)))

__device__ __forceinline__ float f32x2_lo(ull v) {
    return __uint_as_float((unsigned)(v & 0xffffffffu));
}
__device__ __forceinline__ float f32x2_hi(ull v) {
    return __uint_as_float((unsigned)(v >> 32));
}

// ---------------- scratch (static device arrays; no cudaMalloc) -------------
__device__ int   g_cnt[N_NODES];
__device__ int   g_bucket[(size_t)N_NODES * MAXDEG];
__device__ float g_agg1[(size_t)N_NODES * F_IN];
__device__ float g_h1  [(size_t)N_NODES * H1];
__device__ float g_agg2[(size_t)N_NODES * H1];
__device__ float g_h2  [(size_t)N_NODES * H2];
__device__ float g_agg3[(size_t)N_NODES * H2];

// ---------------- bucket build ----------------------------------------------
__global__ void zero_cnt_kernel() {
    int i = blockIdx.x * blockDim.x + threadIdx.x;
    if (i < N_NODES) g_cnt[i] = 0;
}

__global__ void bucket_build_kernel(const int* __restrict__ src,
                                    const int* __restrict__ dst) {
    int e = blockIdx.x * blockDim.x + threadIdx.x;
    if (e >= N_EDGES) return;
    int d = dst[e];
    int p = atomicAdd(&g_cnt[d], 1);
    if (p < MAXDEG) g_bucket[(size_t)d * MAXDEG + p] = src[e];
}

// ---------------- aggregation: warp/node, float2 gather, unroll x2 ----------
template <int F>
__global__ void agg_kernel(const float* __restrict__ x, float* __restrict__ agg) {
    constexpr int C2 = F / 2;
    constexpr int RV = (C2 + 31) / 32;

    int gwarp = (blockIdx.x * blockDim.x + threadIdx.x) >> 5;
    int lane  = threadIdx.x & 31;
    if (gwarp >= N_NODES) return;

    int c = g_cnt[gwarp];
    if (c > MAXDEG) c = MAXDEG;

    float2 m[RV];
#pragma unroll
    for (int r = 0; r < RV; r++) { m[r].x = -INFINITY; m[r].y = -INFINITY; }

    const int* bk = g_bucket + (size_t)gwarp * MAXDEG;
    int i = 0;
    for (; i + 1 < c; i += 2) {
        int s0 = bk[i], s1 = bk[i + 1];
        const float2* r0 = (const float2*)(x + (size_t)s0 * F);
        const float2* r1 = (const float2*)(x + (size_t)s1 * F);
#pragma unroll
        for (int r = 0; r < RV; r++) {
            int ch = lane + r * 32;
            if (ch < C2) {
                float2 v0 = r0[ch];
                float2 v1 = r1[ch];
                m[r].x = fmaxf(m[r].x, fmaxf(v0.x, v1.x));
                m[r].y = fmaxf(m[r].y, fmaxf(v0.y, v1.y));
            }
        }
    }
    if (i < c) {
        const float2* r0 = (const float2*)(x + (size_t)bk[i] * F);
#pragma unroll
        for (int r = 0; r < RV; r++) {
            int ch = lane + r * 32;
            if (ch < C2) {
                float2 v0 = r0[ch];
                m[r].x = fmaxf(m[r].x, v0.x);
                m[r].y = fmaxf(m[r].y, v0.y);
            }
        }
    }

    float2* out = (float2*)(agg + (size_t)gwarp * F);
#pragma unroll
    for (int r = 0; r < RV; r++) {
        int ch = lane + r * 32;
        if (ch < C2) out[ch] = (c == 0) ? make_float2(0.f, 0.f) : m[r];
    }
}

// ---------------- dual GEMM 128x128, 8x8 micro, FFMA2 ----------------------
// acc held as 4 row-pairs x 8 cols of f32x2. Row pairs come directly from the
// transposed As tile (adjacent rows = adjacent floats = one 64-bit lane pair).
__global__ __launch_bounds__(256, 2)
void gemm128_dual(const float* __restrict__ A1, const float* __restrict__ A2,
                  const float* __restrict__ W1, const float* __restrict__ W2,
                  const float* __restrict__ bias, float* __restrict__ out,
                  int M, int K, int NN) {
    constexpr int BM = 128, BN = 128, BK = 8, PAD = 4;
    __shared__ float As[BK][BM + PAD];   // stride 132 floats = 528 B (16B mult)
    __shared__ float Ws[BK][BN + PAD];

    int tid = threadIdx.x;
    int tx = tid & 15;
    int ty = tid >> 4;
    int rowBase = blockIdx.y * BM;
    int colBase = blockIdx.x * BN;

    int ar = tid >> 1;
    int ak = (tid & 1) * 4;
    int wk = tid >> 5;
    int wc = (tid & 31) * 4;

    ull acc[4][8];                       // [row-pair][col] f32x2
#pragma unroll
    for (int p = 0; p < 4; p++)
#pragma unroll
        for (int j = 0; j < 8; j++) acc[p][j] = 0ull;

    for (int kt = 0; kt < 2 * K; kt += BK) {
        const float* A; const float* W; int ko;
        if (kt < K) { A = A1; W = W1; ko = kt; }
        else        { A = A2; W = W2; ko = kt - K; }

        {
            int row = rowBase + ar;
            float4 v = make_float4(0.f, 0.f, 0.f, 0.f);
            if (row < M) v = *(const float4*)(A + (size_t)row * K + ko + ak);
            As[ak + 0][ar] = v.x; As[ak + 1][ar] = v.y;
            As[ak + 2][ar] = v.z; As[ak + 3][ar] = v.w;
        }
        {
            int col = colBase + wc;
            float4 v = make_float4(0.f, 0.f, 0.f, 0.f);
            if (col < NN) v = *(const float4*)(W + (size_t)(ko + wk) * NN + col);
            *(float4*)&Ws[wk][wc] = v;
        }
        __syncthreads();

#pragma unroll
        for (int kk = 0; kk < BK; kk++) {
            // A row-pairs: one LDS.128 yields two 64-bit f32x2 lane pairs.
            ulonglong2 la0 = *(const ulonglong2*)&As[kk][ty * 8];
            ulonglong2 la1 = *(const ulonglong2*)&As[kk][ty * 8 + 4];
            ull a2[4] = {la0.x, la0.y, la1.x, la1.y};

            float4 w0 = *(const float4*)&Ws[kk][tx * 8];
            float4 w1 = *(const float4*)&Ws[kk][tx * 8 + 4];
            float wv[8] = {w0.x, w0.y, w0.z, w0.w, w1.x, w1.y, w1.z, w1.w};
            ull w2[8];
#pragma unroll
            for (int j = 0; j < 8; j++) SPLAT_F32X2(w2[j], wv[j]);

#pragma unroll
            for (int p = 0; p < 4; p++)
#pragma unroll
                for (int j = 0; j < 8; j++)
                    FMA_F32X2(acc[p][j], a2[p], w2[j]);
        }
        __syncthreads();
    }

#pragma unroll
    for (int p = 0; p < 4; p++) {
#pragma unroll
        for (int half = 0; half < 2; half++) {
            int row = rowBase + ty * 8 + p * 2 + half;
            if (row >= M) continue;
#pragma unroll
            for (int jv = 0; jv < 8; jv += 4) {
                int col = colBase + tx * 8 + jv;
                if (col < NN) {
                    float4 bv = *(const float4*)(bias + col);
                    float4 o;
                    o.x = (half ? f32x2_hi(acc[p][jv + 0]) : f32x2_lo(acc[p][jv + 0])) + bv.x;
                    o.y = (half ? f32x2_hi(acc[p][jv + 1]) : f32x2_lo(acc[p][jv + 1])) + bv.y;
                    o.z = (half ? f32x2_hi(acc[p][jv + 2]) : f32x2_lo(acc[p][jv + 2])) + bv.z;
                    o.w = (half ? f32x2_hi(acc[p][jv + 3]) : f32x2_lo(acc[p][jv + 3])) + bv.w;
                    *(float4*)(out + (size_t)row * NN + col) = o;
                }
            }
        }
    }
}

// ---------------- dual GEMM 128x64, 8x4 micro, FFMA2 -----------------------
__global__ __launch_bounds__(256, 2)
void gemm64_dual(const float* __restrict__ A1, const float* __restrict__ A2,
                 const float* __restrict__ W1, const float* __restrict__ W2,
                 const float* __restrict__ bias, float* __restrict__ out,
                 int M, int K, int NN) {
    constexpr int BM = 128, BN = 64, BK = 8, PAD = 4;
    __shared__ float As[BK][BM + PAD];
    __shared__ float Ws[BK][BN + PAD];   // stride 68 floats = 272 B (16B mult)

    int tid = threadIdx.x;
    int tx = tid & 15;
    int ty = tid >> 4;
    int rowBase = blockIdx.y * BM;
    int colBase = blockIdx.x * BN;

    int ar = tid >> 1;
    int ak = (tid & 1) * 4;
    int wk = tid >> 5;
    int wc = (tid & 31) * 2;

    ull acc[4][4];
#pragma unroll
    for (int p = 0; p < 4; p++)
#pragma unroll
        for (int j = 0; j < 4; j++) acc[p][j] = 0ull;

    for (int kt = 0; kt < 2 * K; kt += BK) {
        const float* A; const float* W; int ko;
        if (kt < K) { A = A1; W = W1; ko = kt; }
        else        { A = A2; W = W2; ko = kt - K; }

        {
            int row = rowBase + ar;
            float4 v = make_float4(0.f, 0.f, 0.f, 0.f);
            if (row < M) v = *(const float4*)(A + (size_t)row * K + ko + ak);
            As[ak + 0][ar] = v.x; As[ak + 1][ar] = v.y;
            As[ak + 2][ar] = v.z; As[ak + 3][ar] = v.w;
        }
        {
            int col = colBase + wc;
            float2 v = make_float2(0.f, 0.f);
            if (col < NN) v = *(const float2*)(W + (size_t)(ko + wk) * NN + col);
            *(float2*)&Ws[wk][wc] = v;
        }
        __syncthreads();

#pragma unroll
        for (int kk = 0; kk < BK; kk++) {
            ulonglong2 la0 = *(const ulonglong2*)&As[kk][ty * 8];
            ulonglong2 la1 = *(const ulonglong2*)&As[kk][ty * 8 + 4];
            ull a2[4] = {la0.x, la0.y, la1.x, la1.y};

            float4 w0 = *(const float4*)&Ws[kk][tx * 4];
            float wv[4] = {w0.x, w0.y, w0.z, w0.w};
            ull w2[4];
#pragma unroll
            for (int j = 0; j < 4; j++) SPLAT_F32X2(w2[j], wv[j]);

#pragma unroll
            for (int p = 0; p < 4; p++)
#pragma unroll
                for (int j = 0; j < 4; j++)
                    FMA_F32X2(acc[p][j], a2[p], w2[j]);
        }
        __syncthreads();
    }

#pragma unroll
    for (int p = 0; p < 4; p++) {
#pragma unroll
        for (int half = 0; half < 2; half++) {
            int row = rowBase + ty * 8 + p * 2 + half;
            if (row >= M) continue;
#pragma unroll
            for (int j = 0; j < 4; j++) {
                int col = colBase + tx * 4 + j;
                if (col < NN) {
                    float v = half ? f32x2_hi(acc[p][j]) : f32x2_lo(acc[p][j]);
                    out[(size_t)row * NN + col] = v + bias[col];
                }
            }
        }
    }
}

// ---------------- final layer + log_softmax ---------------------------------
__global__ void final_kernel(const float* __restrict__ agg,
                             const float* __restrict__ h,
                             const float* __restrict__ Wl,
                             const float* __restrict__ Wr,
                             const float* __restrict__ b,
                             float* __restrict__ out) {
    __shared__ float sWl[H2 * C_OUT], sWr[H2 * C_OUT], sb[C_OUT];
    for (int i = threadIdx.x; i < H2 * C_OUT; i += blockDim.x) {
        sWl[i] = Wl[i];
        sWr[i] = Wr[i];
    }
    if (threadIdx.x < C_OUT) sb[threadIdx.x] = b[threadIdx.x];
    __syncthreads();

    int n = blockIdx.x * blockDim.x + threadIdx.x;
    if (n >= N_NODES) return;

    float logit[C_OUT];
#pragma unroll
    for (int j = 0; j < C_OUT; j++) logit[j] = sb[j];

    const float* ar = agg + (size_t)n * H2;
    const float* hr = h   + (size_t)n * H2;
#pragma unroll 5
    for (int k = 0; k < H2; k++) {
        float a  = ar[k];
        float hh = hr[k];
#pragma unroll
        for (int j = 0; j < C_OUT; j++)
            logit[j] += a * sWl[k * C_OUT + j] + hh * sWr[k * C_OUT + j];
    }

    float mx = logit[0];
#pragma unroll
    for (int j = 1; j < C_OUT; j++) mx = fmaxf(mx, logit[j]);
    float s = 0.0f;
#pragma unroll
    for (int j = 0; j < C_OUT; j++) s += expf(logit[j] - mx);
    float lse = mx + logf(s);
#pragma unroll
    for (int j = 0; j < C_OUT; j++) out[(size_t)n * C_OUT + j] = logit[j] - lse;
}

// ---------------- launch ----------------------------------------------------
extern "C" void kernel_launch(void* const* d_in, const int* in_sizes, int n_in,
                              void* d_out, int out_size) {
    const float* x    = (const float*)d_in[0];
    const int*   ei   = (const int*)d_in[1];
    const float* W_l1 = (const float*)d_in[2];
    const float* b1   = (const float*)d_in[3];
    const float* W_r1 = (const float*)d_in[4];
    const float* W_l2 = (const float*)d_in[5];
    const float* b2   = (const float*)d_in[6];
    const float* W_r2 = (const float*)d_in[7];
    const float* W_l3 = (const float*)d_in[8];
    const float* b3   = (const float*)d_in[9];
    const float* W_r3 = (const float*)d_in[10];
    float* out = (float*)d_out;

    const int* src = ei;
    const int* dst = ei + N_EDGES;

    float *agg1, *h1, *agg2, *h2, *agg3;
    cudaGetSymbolAddress((void**)&agg1, g_agg1);
    cudaGetSymbolAddress((void**)&h1,   g_h1);
    cudaGetSymbolAddress((void**)&agg2, g_agg2);
    cudaGetSymbolAddress((void**)&h2,   g_h2);
    cudaGetSymbolAddress((void**)&agg3, g_agg3);

    zero_cnt_kernel<<<(N_NODES + 255) / 256, 256>>>();
    bucket_build_kernel<<<(N_EDGES + 255) / 256, 256>>>(src, dst);

    const int aggBlocks = (N_NODES * 32 + 255) / 256;

    // layer 1
    agg_kernel<F_IN><<<aggBlocks, 256>>>(x, agg1);
    {
        dim3 grid((H1 + 127) / 128, (N_NODES + 127) / 128);
        gemm128_dual<<<grid, 256>>>(agg1, x, W_l1, W_r1, b1, h1,
                                    N_NODES, F_IN, H1);
    }

    // layer 2
    agg_kernel<H1><<<aggBlocks, 256>>>(h1, agg2);
    {
        dim3 grid((H2 + 63) / 64, (N_NODES + 127) / 128);
        gemm64_dual<<<grid, 256>>>(agg2, h1, W_l2, W_r2, b2, h2,
                                   N_NODES, H1, H2);
    }

    // layer 3 + log_softmax
    agg_kernel<H2><<<aggBlocks, 256>>>(h2, agg3);
    final_kernel<<<(N_NODES + 255) / 256, 256>>>(agg3, h2, W_l3, W_r3, b3, out);
}